// round 2
// baseline (speedup 1.0000x reference)
#include <cuda_runtime.h>
#include <cuda_bf16.h>
#include <cstdint>

// Problem constants
#define BB 64
#define CC 128
#define HH 256
#define LLEN 1024
#define GG 1024                 // 4*H
#define WSTRIDE 395264          // per-batch weight stride: G*C + G*H + 2*G
#define WHH_OFF 131072          // G*C
#define B1_OFF 393216           // s1
#define B2_OFF 394240           // s2

// LSTM kernel tuning
#define RRES 160                // resident W_hh rows per CTA (in SMEM), multiple of 32
#define THIST 32                // h history tile (steps)
#define HIST_STRIDE 33          // padded to kill bank conflicts
#define SMEM_FLOATS (256*RRES + 2*GG + HH + HH*HIST_STRIDE)
#define SMEM_BYTES (SMEM_FLOATS * 4)

// 256 MB scratch for xg = x @ W_ih^T + bias, layout [B][L][G]
__device__ float g_xg[(size_t)BB * LLEN * GG];

// ---------------------------------------------------------------------------
// Kernel 1: xg[b][l][g] = sum_c x[b][c][l] * W_ih[b][g][c] + bias[b][g]
// Tiled fp32 GEMM: 64x64 output tile per CTA, C chunked by 32.
// ---------------------------------------------------------------------------
__global__ void xg_kernel(const float* __restrict__ x, const float* __restrict__ w)
{
    __shared__ float xs[32 * 64];   // [c][l]
    __shared__ float ws[32 * 65];   // [c][g], padded row 65 (conflict-free)

    int b  = blockIdx.z;
    int l0 = blockIdx.y * 64;
    int g0 = blockIdx.x * 64;
    int tid = threadIdx.x;          // 256
    int tx = tid & 15;              // -> g (4 per thread)
    int ty = tid >> 4;              // -> l (4 per thread)

    const float* wb = w + (size_t)b * WSTRIDE;
    const float* xb = x + (size_t)b * CC * LLEN;

    float acc[4][4];
#pragma unroll
    for (int i = 0; i < 4; i++)
#pragma unroll
        for (int j = 0; j < 4; j++) acc[i][j] = 0.f;

    for (int kc = 0; kc < CC; kc += 32) {
        // load x chunk: coalesced (l contiguous)
        for (int idx = tid; idx < 32 * 64; idx += 256) {
            int c = idx >> 6, l = idx & 63;
            xs[c * 64 + l] = xb[(size_t)(kc + c) * LLEN + l0 + l];
        }
        // load W_ih chunk: coalesced (c contiguous), store transposed [c][g]
        for (int idx = tid; idx < 64 * 32; idx += 256) {
            int g = idx >> 5, c = idx & 31;
            ws[c * 65 + g] = wb[(size_t)(g0 + g) * CC + kc + c];
        }
        __syncthreads();
#pragma unroll
        for (int c = 0; c < 32; c++) {
            float xv[4], wv[4];
#pragma unroll
            for (int i = 0; i < 4; i++) xv[i] = xs[c * 64 + ty * 4 + i];
#pragma unroll
            for (int i = 0; i < 4; i++) wv[i] = ws[c * 65 + tx * 4 + i];
#pragma unroll
            for (int li = 0; li < 4; li++)
#pragma unroll
                for (int gi = 0; gi < 4; gi++)
                    acc[li][gi] += xv[li] * wv[gi];
        }
        __syncthreads();
    }

    // bias = w[s1+g] + w[s2+g]
    float bias[4];
#pragma unroll
    for (int i = 0; i < 4; i++) {
        int g = g0 + tx * 4 + i;
        bias[i] = wb[B1_OFF + g] + wb[B2_OFF + g];
    }

#pragma unroll
    for (int li = 0; li < 4; li++) {
        float4 v;
        v.x = acc[li][0] + bias[0];
        v.y = acc[li][1] + bias[1];
        v.z = acc[li][2] + bias[2];
        v.w = acc[li][3] + bias[3];
        size_t o = ((size_t)b * LLEN + l0 + ty * 4 + li) * GG + g0 + tx * 4;
        *reinterpret_cast<float4*>(&g_xg[o]) = v;
    }
}

// ---------------------------------------------------------------------------
// Kernel 2: LSTM recurrence. One 2-CTA cluster per batch. CTA rank r owns
// gates [r*512, r*512+512). 160 of its 512 W_hh rows live in SMEM
// (transposed [k][row]); the rest stream from L2 each step. Gates exchanged
// via st.shared::cluster into a double buffer; one cluster barrier per step.
// Both CTAs redundantly compute the full (h, c) pointwise update.
// ---------------------------------------------------------------------------
__device__ __forceinline__ float sigmoidf_(float v) { return 1.f / (1.f + __expf(-v)); }

__global__ void __cluster_dims__(2, 1, 1) __launch_bounds__(512, 1)
lstm_kernel(const float* __restrict__ w, const float* __restrict__ state,
            float* __restrict__ out)
{
    extern __shared__ float sm[];
    float* W_sT  = sm;                         // [256][RRES]
    float* gates = sm + 256 * RRES;            // [2][1024] double-buffered
    float* h_s   = gates + 2 * GG;             // [256]
    float* hist  = h_s + HH;                   // [256][HIST_STRIDE]

    int tid   = threadIdx.x;                   // 512
    int rank  = blockIdx.x & 1;
    int b     = blockIdx.x >> 1;
    int gbase = rank << 9;                     // rank*512

    const float* Wb = w + (size_t)b * WSTRIDE + WHH_OFF;   // [1024][256]

    // Stage resident rows, transposed: W_sT[k*RRES + row] = W[gbase+row][k]
    for (int idx = tid; idx < RRES * 256; idx += 512) {
        int row = idx >> 8, k = idx & 255;
        W_sT[k * RRES + row] = Wb[(size_t)(gbase + row) * HH + k];
    }
    if (tid < HH) h_s[tid] = state[b * 512 + tid];
    float c_reg = (tid < HH) ? state[b * 512 + HH + tid] : 0.f;

    // peer address of gates base in the other CTA's SMEM
    uint32_t gates_u = (uint32_t)__cvta_generic_to_shared(gates);
    uint32_t peer_gates;
    {
        uint32_t pr = rank ^ 1;
        asm("mapa.shared::cluster.u32 %0, %1, %2;"
            : "=r"(peer_gates) : "r"(gates_u), "r"(pr));
    }
    __syncthreads();

    const float* wrow = Wb + (size_t)(gbase + tid) * HH;                 // stream rows
    const float* xgp  = g_xg + (size_t)b * LLEN * GG + gbase + tid;      // step stride GG

    for (int l = 0; l < LLEN; ++l) {
        float acc = xgp[(size_t)l * GG];

        if (tid < RRES) {
            // SMEM-resident weight row (conflict-free: lanes -> consecutive rows)
            float a0 = 0.f, a1 = 0.f, a2 = 0.f, a3 = 0.f;
#pragma unroll 8
            for (int k = 0; k < HH; k += 4) {
                a0 += W_sT[(k + 0) * RRES + tid] * h_s[k + 0];
                a1 += W_sT[(k + 1) * RRES + tid] * h_s[k + 1];
                a2 += W_sT[(k + 2) * RRES + tid] * h_s[k + 2];
                a3 += W_sT[(k + 3) * RRES + tid] * h_s[k + 3];
            }
            acc += (a0 + a1) + (a2 + a3);
        } else {
            // streamed row: per-thread float4 loads, L1 absorbs intra-line reuse
            const float4* w4 = reinterpret_cast<const float4*>(wrow);
            const float4* h4 = reinterpret_cast<const float4*>(h_s);
            float a0 = 0.f, a1 = 0.f;
#pragma unroll 8
            for (int k = 0; k < 64; k += 2) {
                float4 wv0 = w4[k],     hv0 = h4[k];
                float4 wv1 = w4[k + 1], hv1 = h4[k + 1];
                a0 += wv0.x * hv0.x + wv0.y * hv0.y + wv0.z * hv0.z + wv0.w * hv0.w;
                a1 += wv1.x * hv1.x + wv1.y * hv1.y + wv1.z * hv1.z + wv1.w * hv1.w;
            }
            acc += a0 + a1;
        }

        // publish gate: local + peer (double buffer p = l&1)
        int p = l & 1;
        int goff = (p << 10) + gbase + tid;
        gates[goff] = acc;
        asm volatile("st.shared::cluster.f32 [%0], %1;"
                     :: "r"(peer_gates + (uint32_t)goff * 4u), "f"(acc) : "memory");

        // one cluster barrier per step (release/acquire orders the DSMEM stores)
        asm volatile("barrier.cluster.arrive.aligned;" ::: "memory");
        asm volatile("barrier.cluster.wait.aligned;" ::: "memory");

        if (tid < HH) {
            const float* gb = gates + (p << 10);
            float iv = sigmoidf_(gb[tid]);
            float fv = sigmoidf_(gb[HH + tid]);
            float gv = tanhf(gb[2 * HH + tid]);
            float ov = sigmoidf_(gb[3 * HH + tid]);
            c_reg = fv * c_reg + iv * gv;
            float hv = ov * tanhf(c_reg);
            h_s[tid] = hv;
            hist[tid * HIST_STRIDE + (l & (THIST - 1))] = hv;
        }
        __syncthreads();   // h_s ready for next step's GEMV

        // flush 32-step h history: coalesced 128B rows; each rank writes its half
        if ((l & (THIST - 1)) == THIST - 1) {
            int l0 = l - (THIST - 1);
            for (int idx = tid; idx < 128 * THIST; idx += 512) {
                int j = (rank << 7) + (idx >> 5);
                int t = idx & 31;
                out[((size_t)b * HH + j) * LLEN + l0 + t] = hist[j * HIST_STRIDE + t];
            }
            // next hist write happens after the next cluster barrier -> safe
        }
    }

    if (rank == 0 && tid < HH) {
        size_t ysz = (size_t)BB * HH * LLEN;
        out[ysz + (size_t)b * 512 + tid]      = h_s[tid];
        out[ysz + (size_t)b * 512 + HH + tid] = c_reg;
    }
}

// ---------------------------------------------------------------------------
extern "C" void kernel_launch(void* const* d_in, const int* in_sizes, int n_in,
                              void* d_out, int out_size)
{
    const float* x     = (const float*)d_in[0];
    const float* state = (const float*)d_in[1];
    const float* w     = (const float*)d_in[2];
    float* out = (float*)d_out;

    cudaFuncSetAttribute(lstm_kernel,
                         cudaFuncAttributeMaxDynamicSharedMemorySize, SMEM_BYTES);

    xg_kernel<<<dim3(GG / 64, LLEN / 64, BB), 256>>>(x, w);
    lstm_kernel<<<BB * 2, 512, SMEM_BYTES>>>(w, state, out);
}

// round 3
// speedup vs baseline: 3.3403x; 3.3403x over previous
#include <cuda_runtime.h>
#include <cuda_bf16.h>
#include <cstdint>

// Problem constants
#define BB 64
#define CC 128
#define HH 256
#define LLEN 1024
#define GG 1024                 // 4*H
#define WSTRIDE 395264          // per-batch weight stride: G*C + G*H + 2*G
#define WHH_OFF 131072          // G*C
#define B1_OFF 393216           // s1
#define B2_OFF 394240           // s2

// LSTM kernel tuning
#define RRES 192                // resident W_hh rows per CTA (in SMEM)
#define NSTREAM 320             // streamed rows per CTA (RRES + NSTREAM = 512)
#define THIST 16                // h history tile (steps)
#define HIST_STRIDE 17          // padded
#define SMEM_FLOATS (256*RRES + 2*GG + HH + HH*HIST_STRIDE)
#define SMEM_BYTES (SMEM_FLOATS * 4)   // 223232 B

// Scratch: xg = x @ W_ih^T + bias, layout [B][L][G]  (256 MB)
__device__ float g_xg[(size_t)BB * LLEN * GG];
// Scratch: packed streamed W_hh, per (b,rank): [k/4][j<NSTREAM][4k]  (42 MB)
#define WT_CTA (NSTREAM * HH)   // 81920 floats per CTA
__device__ float g_wt[(size_t)BB * 2 * WT_CTA];

// ---------------------------------------------------------------------------
// Kernel 0: pack streamed W_hh rows into coalesced-friendly layout.
// dst[(k>>2)*NSTREAM*4 + j*4 + (k&3)] = W_hh[b][gbase+RRES+j][k]
// ---------------------------------------------------------------------------
__global__ void pack_kernel(const float* __restrict__ w)
{
    int rank = blockIdx.x & 1;
    int b    = blockIdx.x >> 1;
    const float* Wb = w + (size_t)b * WSTRIDE + WHH_OFF
                        + (size_t)(rank * 512 + RRES) * HH;
    float* dst = g_wt + (size_t)blockIdx.x * WT_CTA;
    // iterate over destination (coalesced writes)
    for (int idx = threadIdx.x; idx < WT_CTA; idx += blockDim.x) {
        int kq = idx / (NSTREAM * 4);
        int r  = idx - kq * (NSTREAM * 4);
        int j  = r >> 2;
        int k  = (kq << 2) | (r & 3);
        dst[idx] = Wb[(size_t)j * HH + k];
    }
}

// ---------------------------------------------------------------------------
// Kernel 1: xg[b][l][g] = sum_c x[b][c][l] * W_ih[b][g][c] + bias[b][g]
// ---------------------------------------------------------------------------
__global__ void xg_kernel(const float* __restrict__ x, const float* __restrict__ w)
{
    __shared__ float xs[32 * 64];   // [c][l]
    __shared__ float ws[32 * 65];   // [c][g] padded

    int b  = blockIdx.z;
    int l0 = blockIdx.y * 64;
    int g0 = blockIdx.x * 64;
    int tid = threadIdx.x;
    int tx = tid & 15;
    int ty = tid >> 4;

    const float* wb = w + (size_t)b * WSTRIDE;
    const float* xb = x + (size_t)b * CC * LLEN;

    float acc[4][4];
#pragma unroll
    for (int i = 0; i < 4; i++)
#pragma unroll
        for (int j = 0; j < 4; j++) acc[i][j] = 0.f;

    for (int kc = 0; kc < CC; kc += 32) {
        for (int idx = tid; idx < 32 * 64; idx += 256) {
            int c = idx >> 6, l = idx & 63;
            xs[c * 64 + l] = xb[(size_t)(kc + c) * LLEN + l0 + l];
        }
        for (int idx = tid; idx < 64 * 32; idx += 256) {
            int g = idx >> 5, c = idx & 31;
            ws[c * 65 + g] = wb[(size_t)(g0 + g) * CC + kc + c];
        }
        __syncthreads();
#pragma unroll
        for (int c = 0; c < 32; c++) {
            float xv[4], wv[4];
#pragma unroll
            for (int i = 0; i < 4; i++) xv[i] = xs[c * 64 + ty * 4 + i];
#pragma unroll
            for (int i = 0; i < 4; i++) wv[i] = ws[c * 65 + tx * 4 + i];
#pragma unroll
            for (int li = 0; li < 4; li++)
#pragma unroll
                for (int gi = 0; gi < 4; gi++)
                    acc[li][gi] += xv[li] * wv[gi];
        }
        __syncthreads();
    }

    float bias[4];
#pragma unroll
    for (int i = 0; i < 4; i++) {
        int g = g0 + tx * 4 + i;
        bias[i] = wb[B1_OFF + g] + wb[B2_OFF + g];
    }

#pragma unroll
    for (int li = 0; li < 4; li++) {
        float4 v;
        v.x = acc[li][0] + bias[0];
        v.y = acc[li][1] + bias[1];
        v.z = acc[li][2] + bias[2];
        v.w = acc[li][3] + bias[3];
        size_t o = ((size_t)b * LLEN + l0 + ty * 4 + li) * GG + g0 + tx * 4;
        *reinterpret_cast<float4*>(&g_xg[o]) = v;
    }
}

// ---------------------------------------------------------------------------
// Kernel 2: LSTM recurrence. 2-CTA cluster per batch; CTA owns 512 gates.
// 192 rows resident in SMEM (packed [k/4][row][4k], LDS.128 per thread);
// 320 rows streamed from the packed L2-resident g_wt (LDG.128 per thread,
// lane-consecutive -> 4 lines/warp-instr). One cluster barrier per step.
// ---------------------------------------------------------------------------
__device__ __forceinline__ float sigmoidf_(float v) { return 1.f / (1.f + __expf(-v)); }

__global__ void __cluster_dims__(2, 1, 1) __launch_bounds__(512, 1)
lstm_kernel(const float* __restrict__ w, const float* __restrict__ state,
            float* __restrict__ out)
{
    extern __shared__ float sm[];
    float* W_s4  = sm;                          // [64][RRES][4]  (RRES*256 floats)
    float* gates = sm + 256 * RRES;             // [2][1024]
    float* h_s   = gates + 2 * GG;              // [256]
    float* hist  = h_s + HH;                    // [256][HIST_STRIDE]

    int tid   = threadIdx.x;                    // 512
    int rank  = blockIdx.x & 1;
    int b     = blockIdx.x >> 1;
    int gbase = rank << 9;

    const float* Wb = w + (size_t)b * WSTRIDE + WHH_OFF;

    // Stage resident rows packed: W_s4[(k>>2)*RRES*4 + row*4 + (k&3)]
    for (int idx = tid; idx < RRES * 256; idx += 512) {
        int row = idx >> 8, k = idx & 255;
        W_s4[(k >> 2) * (RRES * 4) + row * 4 + (k & 3)] =
            Wb[(size_t)(gbase + row) * HH + k];
    }
    if (tid < HH) h_s[tid] = state[b * 512 + tid];
    float c_reg = (tid < HH) ? state[b * 512 + HH + tid] : 0.f;

    uint32_t gates_u = (uint32_t)__cvta_generic_to_shared(gates);
    uint32_t peer_gates;
    {
        uint32_t pr = rank ^ 1;
        asm("mapa.shared::cluster.u32 %0, %1, %2;"
            : "=r"(peer_gates) : "r"(gates_u), "r"(pr));
    }
    __syncthreads();

    const float4* wt4 = reinterpret_cast<const float4*>(
        g_wt + (size_t)blockIdx.x * WT_CTA);            // [kq*NSTREAM + j]
    const float4* ws4 = reinterpret_cast<const float4*>(W_s4);
    const float4* h4  = reinterpret_cast<const float4*>(h_s);
    const float* xgp  = g_xg + (size_t)b * LLEN * GG + gbase + tid;
    int jstream = tid - RRES;

    for (int l = 0; l < LLEN; ++l) {
        float acc = xgp[(size_t)l * GG];
        float a0 = 0.f, a1 = 0.f, a2 = 0.f, a3 = 0.f;

        if (tid < RRES) {
#pragma unroll 8
            for (int kq = 0; kq < 64; kq++) {
                float4 wv = ws4[kq * RRES + tid];
                float4 hv = h4[kq];
                a0 += wv.x * hv.x; a1 += wv.y * hv.y;
                a2 += wv.z * hv.z; a3 += wv.w * hv.w;
            }
        } else {
#pragma unroll 8
            for (int kq = 0; kq < 64; kq++) {
                float4 wv = wt4[kq * NSTREAM + jstream];
                float4 hv = h4[kq];
                a0 += wv.x * hv.x; a1 += wv.y * hv.y;
                a2 += wv.z * hv.z; a3 += wv.w * hv.w;
            }
        }
        acc += (a0 + a1) + (a2 + a3);

        int p = l & 1;
        int goff = (p << 10) + gbase + tid;
        gates[goff] = acc;
        asm volatile("st.shared::cluster.f32 [%0], %1;"
                     :: "r"(peer_gates + (uint32_t)goff * 4u), "f"(acc) : "memory");

        asm volatile("barrier.cluster.arrive.aligned;" ::: "memory");
        asm volatile("barrier.cluster.wait.aligned;" ::: "memory");

        if (tid < HH) {
            const float* gb = gates + (p << 10);
            float iv = sigmoidf_(gb[tid]);
            float fv = sigmoidf_(gb[HH + tid]);
            float gv = tanhf(gb[2 * HH + tid]);
            float ov = sigmoidf_(gb[3 * HH + tid]);
            c_reg = fv * c_reg + iv * gv;
            float hv = ov * tanhf(c_reg);
            h_s[tid] = hv;
            hist[tid * HIST_STRIDE + (l & (THIST - 1))] = hv;
        }
        __syncthreads();

        if ((l & (THIST - 1)) == THIST - 1) {
            int l0 = l - (THIST - 1);
            for (int idx = tid; idx < 128 * THIST; idx += 512) {
                int j = (rank << 7) + (idx / THIST);
                int t = idx & (THIST - 1);
                out[((size_t)b * HH + j) * LLEN + l0 + t] =
                    hist[j * HIST_STRIDE + t];
            }
        }
    }

    if (rank == 0 && tid < HH) {
        size_t ysz = (size_t)BB * HH * LLEN;
        out[ysz + (size_t)b * 512 + tid]      = h_s[tid];
        out[ysz + (size_t)b * 512 + HH + tid] = c_reg;
    }
}

// ---------------------------------------------------------------------------
extern "C" void kernel_launch(void* const* d_in, const int* in_sizes, int n_in,
                              void* d_out, int out_size)
{
    const float* x     = (const float*)d_in[0];
    const float* state = (const float*)d_in[1];
    const float* w     = (const float*)d_in[2];
    float* out = (float*)d_out;

    cudaFuncSetAttribute(lstm_kernel,
                         cudaFuncAttributeMaxDynamicSharedMemorySize, SMEM_BYTES);

    pack_kernel<<<BB * 2, 256>>>(w);
    xg_kernel<<<dim3(GG / 64, LLEN / 64, BB), 256>>>(x, w);
    lstm_kernel<<<BB * 2, 512, SMEM_BYTES>>>(w, state, out);
}

// round 5
// speedup vs baseline: 4.1782x; 1.2508x over previous
#include <cuda_runtime.h>
#include <cuda_fp16.h>
#include <cstdint>

// Problem constants
#define BB 64
#define CC 128
#define HH 256
#define LLEN 1024
#define GG 1024                 // 4*H
#define WSTRIDE 395264          // per-batch weight stride
#define WHH_OFF 131072          // G*C
#define B1_OFF 393216
#define B2_OFF 394240

// LSTM tuning: fp16 weights
#define RRES 384                // resident W_hh rows per CTA (SMEM, fp16)
#define NSTREAM 128             // streamed rows per CTA (fp16, packed in L2)
#define THIST 16
#define HIST_STRIDE 17
// SMEM: W 196608 B | gates 8192 B | h 1024 B | hist 17408 B = 223232 B
#define SMEM_W_BYTES (RRES * HH * 2)
#define SMEM_BYTES (SMEM_W_BYTES + 2*GG*4 + HH*4 + HH*HIST_STRIDE*4)

// Scratch: xg = x @ W_ih^T + bias, fp16, layout [B][L][G]  (128 MB)
__device__ __half g_xg[(size_t)BB * LLEN * GG];
// Scratch: packed streamed W_hh fp16, per (b,rank): [k/8][j<NSTREAM][8]  (8 MB)
#define WT_CTA (NSTREAM * HH)
__device__ __half g_wt[(size_t)BB * 2 * WT_CTA];

// ---------------------------------------------------------------------------
// Kernel 0: pack streamed W_hh rows -> fp16, layout [k>>3][j][k&7]
// ---------------------------------------------------------------------------
__global__ void pack_kernel(const float* __restrict__ w)
{
    int rank = blockIdx.x & 1;
    int b    = blockIdx.x >> 1;
    const float* Wb = w + (size_t)b * WSTRIDE + WHH_OFF
                        + (size_t)(rank * 512 + RRES) * HH;
    __half* dst = g_wt + (size_t)blockIdx.x * WT_CTA;
    for (int idx = threadIdx.x; idx < WT_CTA; idx += blockDim.x) {
        int kq = idx / (NSTREAM * 8);
        int r  = idx - kq * (NSTREAM * 8);
        int j  = r >> 3;
        int k  = (kq << 3) | (r & 7);
        dst[idx] = __float2half(Wb[(size_t)j * HH + k]);
    }
}

// ---------------------------------------------------------------------------
// Kernel 1: xg[b][l][g] = sum_c x[b][c][l] * W_ih[b][g][c] + bias -> fp16
// ---------------------------------------------------------------------------
__global__ void xg_kernel(const float* __restrict__ x, const float* __restrict__ w)
{
    __shared__ float xs[32 * 64];
    __shared__ float ws[32 * 65];

    int b  = blockIdx.z;
    int l0 = blockIdx.y * 64;
    int g0 = blockIdx.x * 64;
    int tid = threadIdx.x;
    int tx = tid & 15;
    int ty = tid >> 4;

    const float* wb = w + (size_t)b * WSTRIDE;
    const float* xb = x + (size_t)b * CC * LLEN;

    float acc[4][4];
#pragma unroll
    for (int i = 0; i < 4; i++)
#pragma unroll
        for (int j = 0; j < 4; j++) acc[i][j] = 0.f;

    for (int kc = 0; kc < CC; kc += 32) {
        for (int idx = tid; idx < 32 * 64; idx += 256) {
            int c = idx >> 6, l = idx & 63;
            xs[c * 64 + l] = xb[(size_t)(kc + c) * LLEN + l0 + l];
        }
        for (int idx = tid; idx < 64 * 32; idx += 256) {
            int g = idx >> 5, c = idx & 31;
            ws[c * 65 + g] = wb[(size_t)(g0 + g) * CC + kc + c];
        }
        __syncthreads();
#pragma unroll
        for (int c = 0; c < 32; c++) {
            float xv[4], wv[4];
#pragma unroll
            for (int i = 0; i < 4; i++) xv[i] = xs[c * 64 + ty * 4 + i];
#pragma unroll
            for (int i = 0; i < 4; i++) wv[i] = ws[c * 65 + tx * 4 + i];
#pragma unroll
            for (int li = 0; li < 4; li++)
#pragma unroll
                for (int gi = 0; gi < 4; gi++)
                    acc[li][gi] += xv[li] * wv[gi];
        }
        __syncthreads();
    }

    float bias[4];
#pragma unroll
    for (int i = 0; i < 4; i++) {
        int g = g0 + tx * 4 + i;
        bias[i] = wb[B1_OFF + g] + wb[B2_OFF + g];
    }

#pragma unroll
    for (int li = 0; li < 4; li++) {
        __half2 v01 = __floats2half2_rn(acc[li][0] + bias[0], acc[li][1] + bias[1]);
        __half2 v23 = __floats2half2_rn(acc[li][2] + bias[2], acc[li][3] + bias[3]);
        size_t o = ((size_t)b * LLEN + l0 + ty * 4 + li) * GG + g0 + tx * 4;
        uint2 pk;
        pk.x = *reinterpret_cast<unsigned*>(&v01);
        pk.y = *reinterpret_cast<unsigned*>(&v23);
        *reinterpret_cast<uint2*>(&g_xg[o]) = pk;
    }
}

// ---------------------------------------------------------------------------
// Kernel 2: LSTM recurrence, fp16 weights / fp32 accumulate.
// 2-CTA cluster per batch; CTA owns 512 gates: 384 resident (SMEM fp16,
// packed [k/8][row][8]) + 128 streamed (L2 fp16, packed [k/8][j][8]).
// ---------------------------------------------------------------------------
__device__ __forceinline__ float sigmoidf_(float v) { return 1.f / (1.f + __expf(-v)); }
__device__ __forceinline__ float tanhf_(float v) { return 1.f - 2.f / (__expf(2.f * v) + 1.f); }

__global__ void __cluster_dims__(2, 1, 1) __launch_bounds__(512, 1)
lstm_kernel(const float* __restrict__ w, const float* __restrict__ state,
            float* __restrict__ out)
{
    extern __shared__ __align__(16) char smraw[];
    __half* W_s  = reinterpret_cast<__half*>(smraw);                 // RRES*256 halfs
    float* gates = reinterpret_cast<float*>(smraw + SMEM_W_BYTES);   // [2][1024]
    float* h_s   = gates + 2 * GG;                                   // [256]
    float* hist  = h_s + HH;                                         // [256][17]

    int tid   = threadIdx.x;                    // 512
    int rank  = blockIdx.x & 1;
    int b     = blockIdx.x >> 1;
    int gbase = rank << 9;

    const float* Wb = w + (size_t)b * WSTRIDE + WHH_OFF;

    // Stage resident rows fp16, packed [k>>3][row][k&7]
    for (int idx = tid; idx < RRES * 256; idx += 512) {
        int row = idx >> 8, k = idx & 255;
        W_s[(k >> 3) * (RRES * 8) + row * 8 + (k & 7)] =
            __float2half(Wb[(size_t)(gbase + row) * HH + k]);
    }
    if (tid < HH) h_s[tid] = state[b * 512 + tid];
    float c_reg = (tid < HH) ? state[b * 512 + HH + tid] : 0.f;

    uint32_t gates_u = (uint32_t)__cvta_generic_to_shared(gates);
    uint32_t peer_gates;
    {
        uint32_t pr = rank ^ 1;
        asm("mapa.shared::cluster.u32 %0, %1, %2;"
            : "=r"(peer_gates) : "r"(gates_u), "r"(pr));
    }
    __syncthreads();

    const uint4* ws4 = reinterpret_cast<const uint4*>(W_s);          // [kq*RRES + row]
    const uint4* wt4 = reinterpret_cast<const uint4*>(
        g_wt + (size_t)blockIdx.x * WT_CTA);                          // [kq*NSTREAM + j]
    const float4* h4 = reinterpret_cast<const float4*>(h_s);
    const __half* xgp = g_xg + (size_t)b * LLEN * GG + gbase + tid;
    int jstream = tid - RRES;

    for (int l = 0; l < LLEN; ++l) {
        float acc = __half2float(xgp[(size_t)l * GG]);
        float a0 = 0.f, a1 = 0.f, a2 = 0.f, a3 = 0.f;

        if (tid < RRES) {
#pragma unroll 8
            for (int kq = 0; kq < 32; kq++) {
                uint4 u = ws4[kq * RRES + tid];
                float4 hv0 = h4[2 * kq], hv1 = h4[2 * kq + 1];
                float2 f0 = __half22float2(*reinterpret_cast<__half2*>(&u.x));
                float2 f1 = __half22float2(*reinterpret_cast<__half2*>(&u.y));
                float2 f2 = __half22float2(*reinterpret_cast<__half2*>(&u.z));
                float2 f3 = __half22float2(*reinterpret_cast<__half2*>(&u.w));
                a0 += f0.x * hv0.x; a1 += f0.y * hv0.y;
                a2 += f1.x * hv0.z; a3 += f1.y * hv0.w;
                a0 += f2.x * hv1.x; a1 += f2.y * hv1.y;
                a2 += f3.x * hv1.z; a3 += f3.y * hv1.w;
            }
        } else {
#pragma unroll 8
            for (int kq = 0; kq < 32; kq++) {
                uint4 u = wt4[kq * NSTREAM + jstream];
                float4 hv0 = h4[2 * kq], hv1 = h4[2 * kq + 1];
                float2 f0 = __half22float2(*reinterpret_cast<__half2*>(&u.x));
                float2 f1 = __half22float2(*reinterpret_cast<__half2*>(&u.y));
                float2 f2 = __half22float2(*reinterpret_cast<__half2*>(&u.z));
                float2 f3 = __half22float2(*reinterpret_cast<__half2*>(&u.w));
                a0 += f0.x * hv0.x; a1 += f0.y * hv0.y;
                a2 += f1.x * hv0.z; a3 += f1.y * hv0.w;
                a0 += f2.x * hv1.x; a1 += f2.y * hv1.y;
                a2 += f3.x * hv1.z; a3 += f3.y * hv1.w;
            }
        }
        acc += (a0 + a1) + (a2 + a3);

        int p = l & 1;
        int goff = (p << 10) + gbase + tid;
        gates[goff] = acc;
        asm volatile("st.shared::cluster.f32 [%0], %1;"
                     :: "r"(peer_gates + (uint32_t)goff * 4u), "f"(acc) : "memory");

        asm volatile("barrier.cluster.arrive.aligned;" ::: "memory");
        asm volatile("barrier.cluster.wait.aligned;" ::: "memory");

        if (tid < HH) {
            const float* gb = gates + (p << 10);
            float iv = sigmoidf_(gb[tid]);
            float fv = sigmoidf_(gb[HH + tid]);
            float gv = tanhf_(gb[2 * HH + tid]);
            float ov = sigmoidf_(gb[3 * HH + tid]);
            c_reg = fv * c_reg + iv * gv;
            float hv = ov * tanhf_(c_reg);
            h_s[tid] = hv;
            hist[tid * HIST_STRIDE + (l & (THIST - 1))] = hv;
        }
        __syncthreads();

        if ((l & (THIST - 1)) == THIST - 1) {
            int l0 = l - (THIST - 1);
            for (int idx = tid; idx < 128 * THIST; idx += 512) {
                int j = (rank << 7) + (idx >> 4);
                int t = idx & (THIST - 1);
                out[((size_t)b * HH + j) * LLEN + l0 + t] =
                    hist[j * HIST_STRIDE + t];
            }
        }
    }

    if (rank == 0 && tid < HH) {
        size_t ysz = (size_t)BB * HH * LLEN;
        out[ysz + (size_t)b * 512 + tid]      = h_s[tid];
        out[ysz + (size_t)b * 512 + HH + tid] = c_reg;
    }
}

// ---------------------------------------------------------------------------
extern "C" void kernel_launch(void* const* d_in, const int* in_sizes, int n_in,
                              void* d_out, int out_size)
{
    const float* x     = (const float*)d_in[0];
    const float* state = (const float*)d_in[1];
    const float* w     = (const float*)d_in[2];
    float* out = (float*)d_out;

    cudaFuncSetAttribute(lstm_kernel,
                         cudaFuncAttributeMaxDynamicSharedMemorySize, SMEM_BYTES);

    pack_kernel<<<BB * 2, 256>>>(w);
    xg_kernel<<<dim3(GG / 64, LLEN / 64, BB), 256>>>(x, w);
    lstm_kernel<<<BB * 2, 512, SMEM_BYTES>>>(w, state, out);
}

// round 8
// speedup vs baseline: 4.7077x; 1.1267x over previous
#include <cuda_runtime.h>
#include <cuda_fp16.h>
#include <cstdint>

// Problem constants
#define BB 64
#define CC 128
#define HH 256
#define LLEN 1024
#define GG 1024                 // 4*H
#define WSTRIDE 395264          // per-batch weight stride
#define WHH_OFF 131072          // G*C
#define B1_OFF 393216
#define B2_OFF 394240

// LSTM tuning: fp16 weights, HFMA2 math
#define RRES 384                // resident W_hh rows per CTA (SMEM, fp16)
#define NSTREAM 128             // streamed rows per CTA (fp16, packed in L2)
#define THIST 8
#define HIST_STRIDE 9
#define SMEM_W_BYTES (RRES * HH * 2)        // 196608
// layout: W | gates(2*1024 f32) | h_s(256 f32) | h2(256 f16) | hist(256*9 f32)
#define SMEM_BYTES (SMEM_W_BYTES + 2*GG*4 + HH*4 + HH*2 + HH*HIST_STRIDE*4) // 215552

// Scratch: xg fp16 [B][L][G] (128 MB)
__device__ __half g_xg[(size_t)BB * LLEN * GG];
// Scratch: packed streamed W_hh fp16, per (b,rank): [k/8][j<NSTREAM][8] (8 MB)
#define WT_CTA (NSTREAM * HH)
__device__ __half g_wt[(size_t)BB * 2 * WT_CTA];

// ---------------------------------------------------------------------------
__global__ void pack_kernel(const float* __restrict__ w)
{
    int rank = blockIdx.x & 1;
    int b    = blockIdx.x >> 1;
    const float* Wb = w + (size_t)b * WSTRIDE + WHH_OFF
                        + (size_t)(rank * 512 + RRES) * HH;
    __half* dst = g_wt + (size_t)blockIdx.x * WT_CTA;
    for (int idx = threadIdx.x; idx < WT_CTA; idx += blockDim.x) {
        int kq = idx / (NSTREAM * 8);
        int r  = idx - kq * (NSTREAM * 8);
        int j  = r >> 3;
        int k  = (kq << 3) | (r & 7);
        dst[idx] = __float2half(Wb[(size_t)j * HH + k]);
    }
}

// ---------------------------------------------------------------------------
// Kernel 1: xg[b][l][g] = sum_c x[b][c][l] * W_ih[b][g][c] + bias -> fp16
// ---------------------------------------------------------------------------
__global__ void xg_kernel(const float* __restrict__ x, const float* __restrict__ w)
{
    __shared__ float xs[32 * 64];
    __shared__ float ws[32 * 65];

    int b  = blockIdx.z;
    int l0 = blockIdx.y * 64;
    int g0 = blockIdx.x * 64;
    int tid = threadIdx.x;
    int tx = tid & 15;
    int ty = tid >> 4;

    const float* wb = w + (size_t)b * WSTRIDE;
    const float* xb = x + (size_t)b * CC * LLEN;

    float acc[4][4];
#pragma unroll
    for (int i = 0; i < 4; i++)
#pragma unroll
        for (int j = 0; j < 4; j++) acc[i][j] = 0.f;

    for (int kc = 0; kc < CC; kc += 32) {
        for (int idx = tid; idx < 32 * 64; idx += 256) {
            int c = idx >> 6, l = idx & 63;
            xs[c * 64 + l] = xb[(size_t)(kc + c) * LLEN + l0 + l];
        }
        for (int idx = tid; idx < 64 * 32; idx += 256) {
            int g = idx >> 5, c = idx & 31;
            ws[c * 65 + g] = wb[(size_t)(g0 + g) * CC + kc + c];
        }
        __syncthreads();
#pragma unroll
        for (int c = 0; c < 32; c++) {
            float xv[4], wv[4];
#pragma unroll
            for (int i = 0; i < 4; i++) xv[i] = xs[c * 64 + ty * 4 + i];
#pragma unroll
            for (int i = 0; i < 4; i++) wv[i] = ws[c * 65 + tx * 4 + i];
#pragma unroll
            for (int li = 0; li < 4; li++)
#pragma unroll
                for (int gi = 0; gi < 4; gi++)
                    acc[li][gi] += xv[li] * wv[gi];
        }
        __syncthreads();
    }

    float bias[4];
#pragma unroll
    for (int i = 0; i < 4; i++) {
        int g = g0 + tx * 4 + i;
        bias[i] = wb[B1_OFF + g] + wb[B2_OFF + g];
    }

#pragma unroll
    for (int li = 0; li < 4; li++) {
        __half2 v01 = __floats2half2_rn(acc[li][0] + bias[0], acc[li][1] + bias[1]);
        __half2 v23 = __floats2half2_rn(acc[li][2] + bias[2], acc[li][3] + bias[3]);
        size_t o = ((size_t)b * LLEN + l0 + ty * 4 + li) * GG + g0 + tx * 4;
        uint2 pk;
        pk.x = *reinterpret_cast<unsigned*>(&v01);
        pk.y = *reinterpret_cast<unsigned*>(&v23);
        *reinterpret_cast<uint2*>(&g_xg[o]) = pk;
    }
}

// ---------------------------------------------------------------------------
// Kernel 2: LSTM recurrence. fp16 weights + fp16 h, HFMA2 inner product,
// 16-term fp16 partials folded into fp32. 2-CTA cluster per batch.
// ---------------------------------------------------------------------------
__device__ __forceinline__ float sigmoidf_(float v) { return 1.f / (1.f + __expf(-v)); }
__device__ __forceinline__ float tanhf_(float v) { return 1.f - 2.f / (__expf(2.f * v) + 1.f); }

__global__ void __cluster_dims__(2, 1, 1) __launch_bounds__(512, 1)
lstm_kernel(const float* __restrict__ w, const float* __restrict__ state,
            float* __restrict__ out)
{
    extern __shared__ __align__(16) char smraw[];
    __half* W_s  = reinterpret_cast<__half*>(smraw);                 // RRES*256
    float* gates = reinterpret_cast<float*>(smraw + SMEM_W_BYTES);   // [2][1024]
    float* h_s   = gates + 2 * GG;                                   // [256] f32
    __half* h2_s = reinterpret_cast<__half*>(h_s + HH);              // [256] f16
    float* hist  = reinterpret_cast<float*>(h_s + HH + HH / 2);      // [256][9]

    int tid   = threadIdx.x;                    // 512
    int rank  = blockIdx.x & 1;
    int b     = blockIdx.x >> 1;
    int gbase = rank << 9;

    const float* Wb = w + (size_t)b * WSTRIDE + WHH_OFF;

    // Stage resident rows fp16, packed [k>>3][row][k&7]
    for (int idx = tid; idx < RRES * 256; idx += 512) {
        int row = idx >> 8, k = idx & 255;
        W_s[(k >> 3) * (RRES * 8) + row * 8 + (k & 7)] =
            __float2half(Wb[(size_t)(gbase + row) * HH + k]);
    }
    if (tid < HH) {
        float hv0 = state[b * 512 + tid];
        h_s[tid]  = hv0;
        h2_s[tid] = __float2half(hv0);
    }
    float c_reg = (tid < HH) ? state[b * 512 + HH + tid] : 0.f;

    uint32_t gates_u = (uint32_t)__cvta_generic_to_shared(gates);
    uint32_t peer_gates;
    {
        uint32_t pr = rank ^ 1;
        asm("mapa.shared::cluster.u32 %0, %1, %2;"
            : "=r"(peer_gates) : "r"(gates_u), "r"(pr));
    }
    __syncthreads();

    const uint4* ws4 = reinterpret_cast<const uint4*>(W_s);          // [kq*RRES + row]
    const uint4* wt4 = reinterpret_cast<const uint4*>(
        g_wt + (size_t)blockIdx.x * WT_CTA);                          // [kq*NSTREAM + j]
    const uint4* h2u = reinterpret_cast<const uint4*>(h2_s);          // 32 x 8 halfs
    const __half* xgp = g_xg + (size_t)b * LLEN * GG + gbase + tid;
    bool resident = (tid < RRES);
    const uint4* wsrc = resident ? (ws4 + tid) : (wt4 + (tid - RRES));
    int wpitch = resident ? RRES : NSTREAM;

    for (int l = 0; l < LLEN; ++l) {
        float acc = __half2float(xgp[(size_t)l * GG]);
        float fa0 = 0.f, fa1 = 0.f;

#pragma unroll 4
        for (int i = 0; i < 16; i++) {
            uint4 wa = wsrc[(2 * i) * wpitch];
            uint4 wb2 = wsrc[(2 * i + 1) * wpitch];
            uint4 ha = h2u[2 * i];
            uint4 hb = h2u[2 * i + 1];
            const __half2* wv0 = reinterpret_cast<const __half2*>(&wa);
            const __half2* wv1 = reinterpret_cast<const __half2*>(&wb2);
            const __half2* hv0 = reinterpret_cast<const __half2*>(&ha);
            const __half2* hv1 = reinterpret_cast<const __half2*>(&hb);
            __half2 p = __hfma2(wv0[0], hv0[0], __hmul2(wv0[1], hv0[1]));
            p = __hfma2(wv0[2], hv0[2], p);
            p = __hfma2(wv0[3], hv0[3], p);
            p = __hfma2(wv1[0], hv1[0], p);
            p = __hfma2(wv1[1], hv1[1], p);
            p = __hfma2(wv1[2], hv1[2], p);
            p = __hfma2(wv1[3], hv1[3], p);
            float2 f = __half22float2(p);
            fa0 += f.x; fa1 += f.y;
        }
        acc += fa0 + fa1;

        int p = l & 1;
        int goff = (p << 10) + gbase + tid;
        gates[goff] = acc;
        asm volatile("st.shared::cluster.f32 [%0], %1;"
                     :: "r"(peer_gates + (uint32_t)goff * 4u), "f"(acc) : "memory");

        asm volatile("barrier.cluster.arrive.aligned;" ::: "memory");
        asm volatile("barrier.cluster.wait.aligned;" ::: "memory");

        if (tid < HH) {
            const float* gb = gates + (p << 10);
            float iv = sigmoidf_(gb[tid]);
            float fv = sigmoidf_(gb[HH + tid]);
            float gv = tanhf_(gb[2 * HH + tid]);
            float ov = sigmoidf_(gb[3 * HH + tid]);
            c_reg = fv * c_reg + iv * gv;
            float hv = ov * tanhf_(c_reg);
            h_s[tid]  = hv;
            h2_s[tid] = __float2half(hv);
            hist[tid * HIST_STRIDE + (l & (THIST - 1))] = hv;
        }
        __syncthreads();

        if ((l & (THIST - 1)) == THIST - 1) {
            int l0 = l - (THIST - 1);
            for (int idx = tid; idx < 128 * THIST; idx += 512) {
                int j = (rank << 7) + (idx >> 3);
                int t = idx & (THIST - 1);
                out[((size_t)b * HH + j) * LLEN + l0 + t] =
                    hist[j * HIST_STRIDE + t];
            }
        }
    }

    if (rank == 0 && tid < HH) {
        size_t ysz = (size_t)BB * HH * LLEN;
        out[ysz + (size_t)b * 512 + tid]      = h_s[tid];
        out[ysz + (size_t)b * 512 + HH + tid] = c_reg;
    }
}

// ---------------------------------------------------------------------------
extern "C" void kernel_launch(void* const* d_in, const int* in_sizes, int n_in,
                              void* d_out, int out_size)
{
    const float* x     = (const float*)d_in[0];
    const float* state = (const float*)d_in[1];
    const float* w     = (const float*)d_in[2];
    float* out = (float*)d_out;

    cudaFuncSetAttribute(lstm_kernel,
                         cudaFuncAttributeMaxDynamicSharedMemorySize, SMEM_BYTES);

    pack_kernel<<<BB * 2, 256>>>(w);
    xg_kernel<<<dim3(GG / 64, LLEN / 64, BB), 256>>>(x, w);
    lstm_kernel<<<BB * 2, 512, SMEM_BYTES>>>(w, state, out);
}